// round 9
// baseline (speedup 1.0000x reference)
#include <cuda_runtime.h>
#include <cuda_bf16.h>
#include <cstdint>

#define DT_STEP 0.01f
#define GRID_SMS 152
#define NUM_S32 4096                    // 131072 rows / 32
#define NTHREADS 768
#define NQUADS_CTA 6
#define ROW_B 272                       // 128 bf16 (256B) + 16B pad
#define T32 (32 * ROW_B)                // 32-row strip = 8704 B

#define S_W1  0
#define S_W2  (S_W1 + 128 * ROW_B)
#define S_B1  (S_W2 + 128 * ROW_B)
#define S_B2  (S_B1 + 512)
#define S_POP (S_B2 + 512)              // per-quad popped unit ids
#define S_Q   (S_POP + 512)
#define S_TOT (S_Q + NQUADS_CTA * 2 * T32)   // 71168 + 104448 = 175616 B

__device__ unsigned int g_ctr;

__global__ void reset_ctr() { g_ctr = 0u; }

// ---------------- helpers ----------------
static __device__ __forceinline__ uint32_t smem_u32(const void* p) {
    uint32_t a;
    asm("{ .reg .u64 t; cvta.to.shared.u64 t, %1; cvt.u32.u64 %0, t; }" : "=r"(a) : "l"(p));
    return a;
}

static __device__ __forceinline__ uint32_t packbf(float a, float b) {
    __nv_bfloat162 t = __floats2bfloat162_rn(a, b);   // .x in low 16 bits
    return *reinterpret_cast<uint32_t*>(&t);
}

static __device__ __forceinline__ float tanh_fast(float v) {
    float r;
    asm("tanh.approx.f32 %0, %1;" : "=f"(r) : "f"(v));
    return r;
}

static __device__ __forceinline__ void ldsm_x4(uint32_t* r, uint32_t addr) {
    asm volatile("ldmatrix.sync.aligned.m8n8.x4.shared.b16 {%0,%1,%2,%3}, [%4];"
                 : "=r"(r[0]), "=r"(r[1]), "=r"(r[2]), "=r"(r[3]) : "r"(addr));
}

static __device__ __forceinline__ void ldsm_x4_t(uint32_t* r, uint32_t addr) {
    asm volatile("ldmatrix.sync.aligned.m8n8.x4.trans.shared.b16 {%0,%1,%2,%3}, [%4];"
                 : "=r"(r[0]), "=r"(r[1]), "=r"(r[2]), "=r"(r[3]) : "r"(addr));
}

static __device__ __forceinline__ void mma16816(float* d, const uint32_t* a, const uint32_t* b) {
    asm volatile("mma.sync.aligned.m16n8k16.row.col.f32.bf16.bf16.f32 "
                 "{%0,%1,%2,%3}, {%4,%5,%6,%7}, {%8,%9}, {%0,%1,%2,%3};"
                 : "+f"(d[0]), "+f"(d[1]), "+f"(d[2]), "+f"(d[3])
                 : "r"(a[0]), "r"(a[1]), "r"(a[2]), "r"(a[3]), "r"(b[0]), "r"(b[1]));
}

// ---------------- kernel ----------------
__global__ void __launch_bounds__(NTHREADS, 1)
koopman_queue(const float* __restrict__ x, const float* __restrict__ W1,
              const float* __restrict__ b1, const float* __restrict__ W2,
              const float* __restrict__ b2, float* __restrict__ out)
{
    extern __shared__ char smem[];
    const uint32_t sb = smem_u32(smem);
    const int tid  = threadIdx.x;
    const int lane = tid & 31;
    const int w    = tid >> 5;          // 0..23
    const int quad = w >> 2;            // 0..5
    const int qw   = w & 3;             // N-quarter owner
    const int g    = lane >> 2;
    const int t2   = (lane & 3) * 2;
    const int barid = quad + 1;

    // ---- one-time: stage W1, W2 (bf16, padded rows) + biases ----
    for (int idx = tid; idx < 4096; idx += NTHREADS) {
        int r = idx >> 5, c4 = idx & 31;
        float4 wv = *(const float4*)(W1 + (size_t)r * 128 + c4 * 4);
        *(uint2*)(smem + S_W1 + r * ROW_B + c4 * 8) =
            make_uint2(packbf(wv.x, wv.y), packbf(wv.z, wv.w));
        float4 wv2 = *(const float4*)(W2 + (size_t)r * 128 + c4 * 4);
        *(uint2*)(smem + S_W2 + r * ROW_B + c4 * 8) =
            make_uint2(packbf(wv2.x, wv2.y), packbf(wv2.z, wv2.w));
    }
    if (tid < 128) {
        ((float*)(smem + S_B1))[tid] = b1[tid];
        ((float*)(smem + S_B2))[tid] = b2[tid];
    }
    __syncthreads();                    // only CTA-wide sync

    const uint32_t qoff = (uint32_t)(S_Q + quad * 2 * T32);   // x strip
    const uint32_t hoff = qoff + T32;                          // H strip
    const uint32_t wl1 = sb + S_W1 + (uint32_t)lane * ROW_B + (uint32_t)qw * 64;
    const uint32_t wl2 = sb + S_W2 + (uint32_t)lane * ROW_B + (uint32_t)qw * 64;
    const float* fb1 = (const float*)(smem + S_B1) + qw * 32 + t2;
    const float* fb2 = (const float*)(smem + S_B2) + qw * 32 + t2;
    volatile int* pop = (volatile int*)(smem + S_POP) + quad;

    const uint32_t amBase = (uint32_t)((lane & 7) + ((lane >> 3) & 1) * 8) * ROW_B
                          + (uint32_t)(lane >> 4) * 16;
    const int srow = qw * 8;            // this warp's staging rows

    // ---- pop first unit ----
    if (qw == 0 && lane == 0) *pop = (int)atomicAdd(&g_ctr, 1u);
    asm volatile("bar.sync %0, 128;" :: "r"(barid) : "memory");
    int s = *pop;

    while (s < NUM_S32) {
        const size_t rbase = (size_t)s * 32;

        // ---- stage this unit's x (hi bf16) ----
        {
            const float* xr = x + (rbase + (size_t)srow) * 128 + lane * 4;
            #pragma unroll
            for (int i = 0; i < 8; i++) {
                float4 v = *(const float4*)(xr + (size_t)i * 128);
                *(uint2*)(smem + qoff + (srow + i) * ROW_B + lane * 8) =
                    make_uint2(packbf(v.x, v.y), packbf(v.z, v.w));
            }
        }
        asm volatile("bar.sync %0, 128;" :: "r"(barid) : "memory");   // x ready

        // ---- GEMM1: acc = Xhi(32 rows) @ W1(:, quarter) ----
        float acc[4][2][4];
        #pragma unroll
        for (int nt = 0; nt < 4; nt++)
            #pragma unroll
            for (int mt = 0; mt < 2; mt++)
                { acc[nt][mt][0]=0.f; acc[nt][mt][1]=0.f; acc[nt][mt][2]=0.f; acc[nt][mt][3]=0.f; }
        #pragma unroll
        for (int kh = 0; kh < 2; kh++) {
            uint32_t afr[2][4][4];
            #pragma unroll
            for (int mt = 0; mt < 2; mt++)
                #pragma unroll
                for (int j = 0; j < 4; j++)
                    ldsm_x4(afr[mt][j], sb + qoff + amBase + (uint32_t)(mt * 16) * ROW_B
                                        + (uint32_t)(kh * 4 + j) * 32);
            #pragma unroll
            for (int nt = 0; nt < 4; nt++) {
                uint32_t b[2][4];
                ldsm_x4_t(b[0], wl1 + (uint32_t)(kh * 2 + 0) * (32 * ROW_B) + nt * 16);
                ldsm_x4_t(b[1], wl1 + (uint32_t)(kh * 2 + 1) * (32 * ROW_B) + nt * 16);
                #pragma unroll
                for (int mt = 0; mt < 2; mt++)
                    #pragma unroll
                    for (int j = 0; j < 4; j++)
                        mma16816(acc[nt][mt], afr[mt][j], &b[j >> 1][(j & 1) * 2]);
            }
        }

        // ---- epilogue 1: H quarter = tanh(acc + b1) -> H strip ----
        #pragma unroll
        for (int nt = 0; nt < 4; nt++) {
            float2 bb = *(const float2*)(fb1 + nt * 8);
            int c = qw * 32 + nt * 8 + t2;
            #pragma unroll
            for (int mt = 0; mt < 2; mt++) {
                uint32_t p0 = packbf(tanh_fast(acc[nt][mt][0] + bb.x),
                                     tanh_fast(acc[nt][mt][1] + bb.y));
                uint32_t p1 = packbf(tanh_fast(acc[nt][mt][2] + bb.x),
                                     tanh_fast(acc[nt][mt][3] + bb.y));
                *(uint32_t*)(smem + hoff + (mt * 16 + g) * ROW_B + c * 2) = p0;
                *(uint32_t*)(smem + hoff + (mt * 16 + g + 8) * ROW_B + c * 2) = p1;
            }
        }
        // pop next unit; the same barrier publishes H and the popped id
        if (qw == 0 && lane == 0) *pop = (int)atomicAdd(&g_ctr, 1u);
        asm volatile("bar.sync %0, 128;" :: "r"(barid) : "memory");   // H + pop ready

        // ---- GEMM2: acc = H(32 rows) @ W2(:, quarter) ----
        #pragma unroll
        for (int nt = 0; nt < 4; nt++)
            #pragma unroll
            for (int mt = 0; mt < 2; mt++)
                { acc[nt][mt][0]=0.f; acc[nt][mt][1]=0.f; acc[nt][mt][2]=0.f; acc[nt][mt][3]=0.f; }
        #pragma unroll
        for (int kh = 0; kh < 2; kh++) {
            uint32_t afr[2][4][4];
            #pragma unroll
            for (int mt = 0; mt < 2; mt++)
                #pragma unroll
                for (int j = 0; j < 4; j++)
                    ldsm_x4(afr[mt][j], sb + hoff + amBase + (uint32_t)(mt * 16) * ROW_B
                                        + (uint32_t)(kh * 4 + j) * 32);
            #pragma unroll
            for (int nt = 0; nt < 4; nt++) {
                uint32_t b[2][4];
                ldsm_x4_t(b[0], wl2 + (uint32_t)(kh * 2 + 0) * (32 * ROW_B) + nt * 16);
                ldsm_x4_t(b[1], wl2 + (uint32_t)(kh * 2 + 1) * (32 * ROW_B) + nt * 16);
                #pragma unroll
                for (int mt = 0; mt < 2; mt++)
                    #pragma unroll
                    for (int j = 0; j < 4; j++)
                        mma16816(acc[nt][mt], afr[mt][j], &b[j >> 1][(j & 1) * 2]);
            }
        }

        // ---- epilogue 2: rotation-scaling on exact fp32 x from gmem ----
        #pragma unroll
        for (int nt = 0; nt < 4; nt++) {
            int c = qw * 32 + nt * 8 + t2;
            float2 bb = *(const float2*)(fb2 + nt * 8);
            #pragma unroll
            for (int mt = 0; mt < 2; mt++)
                #pragma unroll
                for (int half = 0; half < 2; half++) {
                    float mu = acc[nt][mt][half * 2 + 0] + bb.x;
                    float om = acc[nt][mt][half * 2 + 1] + bb.y;
                    size_t r = rbase + (size_t)(mt * 16 + g + half * 8);
                    float2 xv = *(const float2*)(x + r * 128 + c);
                    float z  = DT_STEP * mu;
                    float e  = fmaf(z, fmaf(z, fmaf(z, 1.f / 6.f, 0.5f), 1.f), 1.f);
                    float wv = DT_STEP * om;
                    float w2 = wv * wv;
                    float sn = wv * fmaf(w2, -1.f / 6.f, 1.f);
                    float cs = fmaf(w2, fmaf(w2, 1.f / 24.f, -0.5f), 1.f);
                    float2 o;
                    o.x = e * (cs * xv.x - sn * xv.y);
                    o.y = e * (sn * xv.x + cs * xv.y);
                    *(float2*)(out + r * 128 + c) = o;
                }
        }
        asm volatile("bar.sync %0, 128;" :: "r"(barid) : "memory");   // strips reusable
        s = *pop;
    }
}

// ---------------- launch ----------------
extern "C" void kernel_launch(void* const* d_in, const int* in_sizes, int n_in,
                              void* d_out, int out_size) {
    const float* x  = (const float*)d_in[0];
    const float* W1 = (const float*)d_in[1];
    const float* b1 = (const float*)d_in[2];
    const float* W2 = (const float*)d_in[3];
    const float* b2 = (const float*)d_in[4];
    float* out = (float*)d_out;

    cudaFuncSetAttribute(koopman_queue,
                         cudaFuncAttributeMaxDynamicSharedMemorySize, S_TOT);
    reset_ctr<<<1, 1>>>();
    koopman_queue<<<GRID_SMS, NTHREADS, S_TOT>>>(x, W1, b1, W2, b2, out);
}